// round 3
// baseline (speedup 1.0000x reference)
#include <cuda_runtime.h>

#define NDIM 4096
#define RPB  4            // rows per block

// Inter-layer spike vectors (scratch via __device__ globals — no allocation).
__device__ float g_enc[NDIM];
__device__ float g_s0[NDIM];
__device__ float g_s1[NDIM];

// Rate-coding encoder: enc_i = (u_i < x_i) ? 1 : 0.
__global__ void enc_k(const float* __restrict__ x, const float* __restrict__ u) {
    int i = blockIdx.x * blockDim.x + threadIdx.x;
    if (i < NDIM) g_enc[i] = (u[i] < x[i]) ? 1.0f : 0.0f;
}

// Masked matvec + threshold. RPB rows per block; 256 threads.
// Spike vector staged in shared once per block. W/M streamed with __ldcs
// (read-once, evict-first), all 8 DRAM loads per row issued before any FMA.
//  IN : 0 -> g_enc, 1 -> g_s0, 2 -> g_s1
//  OUT: 0 -> g_s0,  1 -> g_s1, 2 -> out[row] = spk / T
template<int IN, int OUT>
__global__ __launch_bounds__(256) void layer_k(const float* __restrict__ W,
                                               const float* __restrict__ M,
                                               const int* __restrict__ Tp,
                                               float* __restrict__ out) {
    __shared__ float4 ssp[NDIM / 4];      // 16 KB staged spike vector
    __shared__ float  red[8];

    const float* s = (IN == 0) ? g_enc : (IN == 1) ? g_s0 : g_s1;
    const float4* __restrict__ sg = reinterpret_cast<const float4*>(s);
    for (int i = threadIdx.x; i < NDIM / 4; i += 256) ssp[i] = sg[i];
    __syncthreads();

#pragma unroll 1
    for (int r = 0; r < RPB; r++) {
        const int row = blockIdx.x * RPB + r;
        const float4* __restrict__ w4 =
            reinterpret_cast<const float4*>(W) + (size_t)row * (NDIM / 4);
        const float4* __restrict__ m4 =
            reinterpret_cast<const float4*>(M) + (size_t)row * (NDIM / 4);

        // Front-batch all DRAM loads for this row (8 × 16B outstanding).
        float4 w[4], m[4];
#pragma unroll
        for (int k = 0; k < 4; k++) {
            const int idx = threadIdx.x + k * 256;
            w[k] = __ldcs(w4 + idx);
            m[k] = __ldcs(m4 + idx);
        }

        float acc = 0.0f;
#pragma unroll
        for (int k = 0; k < 4; k++) {
            const int idx = threadIdx.x + k * 256;
            const float4 sv = ssp[idx];
            acc = fmaf(w[k].x * m[k].x, sv.x, acc);
            acc = fmaf(w[k].y * m[k].y, sv.y, acc);
            acc = fmaf(w[k].z * m[k].z, sv.z, acc);
            acc = fmaf(w[k].w * m[k].w, sv.w, acc);
        }

        // Warp reduce
#pragma unroll
        for (int o = 16; o; o >>= 1) acc += __shfl_xor_sync(0xffffffffu, acc, o);

        if ((threadIdx.x & 31) == 0) red[threadIdx.x >> 5] = acc;
        __syncthreads();

        if (threadIdx.x == 0) {
            float t = 0.0f;
#pragma unroll
            for (int i = 0; i < 8; i++) t += red[i];
            const float spk = (t > 1.0f) ? 1.0f : 0.0f;   // THRESH = 1.0
            if (OUT == 0)      g_s0[row] = spk;
            else if (OUT == 1) g_s1[row] = spk;
            else {
                const int T = Tp ? *Tp : 128;
                out[row] = spk / (float)T;                // spikes only at t=0
            }
        }
        __syncthreads();   // protect red[] before next row
    }
}

extern "C" void kernel_launch(void* const* d_in, const int* in_sizes, int n_in,
                              void* d_out, int out_size) {
    const float* x  = (const float*)d_in[0];
    const float* u  = (const float*)d_in[1];
    const float* W0 = (const float*)d_in[2];
    const float* W1 = (const float*)d_in[3];
    const float* W2 = (const float*)d_in[4];
    const float* M0 = (const float*)d_in[5];
    const float* M1 = (const float*)d_in[6];
    const float* M2 = (const float*)d_in[7];
    const int*   T  = (n_in > 8) ? (const int*)d_in[8] : nullptr;
    float* out = (float*)d_out;

    enc_k<<<NDIM / 256, 256>>>(x, u);
    layer_k<0, 0><<<NDIM / RPB, 256>>>(W0, M0, nullptr, nullptr);
    layer_k<1, 1><<<NDIM / RPB, 256>>>(W1, M1, nullptr, nullptr);
    layer_k<2, 2><<<NDIM / RPB, 256>>>(W2, M2, T, out);
}

// round 4
// speedup vs baseline: 1.2241x; 1.2241x over previous
#include <cuda_runtime.h>

#define NDIM 4096
#define WARPS_PER_BLOCK 8

// Inter-layer spike vectors (scratch via __device__ globals — no allocation).
__device__ float g_enc[NDIM];
__device__ float g_s0[NDIM];
__device__ float g_s1[NDIM];

// Rate-coding encoder: enc_i = (u_i < x_i) ? 1 : 0.
__global__ void enc_k(const float* __restrict__ x, const float* __restrict__ u) {
    int i = blockIdx.x * blockDim.x + threadIdx.x;
    if (i < NDIM) g_enc[i] = (u[i] < x[i]) ? 1.0f : 0.0f;
}

// Masked matvec + threshold, ONE WARP PER ROW.
// Zero block-level barriers: each warp streams its 32 KB row (W+M) with
// __ldcs (evict-first) and reduces via shuffles only. Spike vector read via
// __ldg — 16 KB, L1-resident across all warps of the block.
//  IN : 0 -> g_enc, 1 -> g_s0, 2 -> g_s1
//  OUT: 0 -> g_s0,  1 -> g_s1, 2 -> out[row] = spk / T
template<int IN, int OUT>
__global__ __launch_bounds__(WARPS_PER_BLOCK * 32)
void layer_k(const float* __restrict__ W,
             const float* __restrict__ M,
             const int* __restrict__ Tp,
             float* __restrict__ out) {
    const float* s = (IN == 0) ? g_enc : (IN == 1) ? g_s0 : g_s1;
    const int warp = threadIdx.x >> 5;
    const int lane = threadIdx.x & 31;
    const int row  = blockIdx.x * WARPS_PER_BLOCK + warp;

    const float4* __restrict__ w4 =
        reinterpret_cast<const float4*>(W) + (size_t)row * (NDIM / 4);
    const float4* __restrict__ m4 =
        reinterpret_cast<const float4*>(M) + (size_t)row * (NDIM / 4);
    const float4* __restrict__ s4 = reinterpret_cast<const float4*>(s);

    // 32 float4 per lane, coalesced (lane + k*32), 4 independent acc chains.
    float a0 = 0.0f, a1 = 0.0f, a2 = 0.0f, a3 = 0.0f;
#pragma unroll
    for (int k = 0; k < NDIM / 4 / 32; k += 4) {
        const int i0 = lane + (k + 0) * 32;
        const int i1 = lane + (k + 1) * 32;
        const int i2 = lane + (k + 2) * 32;
        const int i3 = lane + (k + 3) * 32;
        const float4 w0 = __ldcs(w4 + i0), m0 = __ldcs(m4 + i0);
        const float4 w1 = __ldcs(w4 + i1), m1 = __ldcs(m4 + i1);
        const float4 w2 = __ldcs(w4 + i2), m2 = __ldcs(m4 + i2);
        const float4 w3 = __ldcs(w4 + i3), m3 = __ldcs(m4 + i3);
        const float4 v0 = __ldg(s4 + i0);
        const float4 v1 = __ldg(s4 + i1);
        const float4 v2 = __ldg(s4 + i2);
        const float4 v3 = __ldg(s4 + i3);
        a0 = fmaf(w0.x * m0.x, v0.x, a0); a0 = fmaf(w0.y * m0.y, v0.y, a0);
        a0 = fmaf(w0.z * m0.z, v0.z, a0); a0 = fmaf(w0.w * m0.w, v0.w, a0);
        a1 = fmaf(w1.x * m1.x, v1.x, a1); a1 = fmaf(w1.y * m1.y, v1.y, a1);
        a1 = fmaf(w1.z * m1.z, v1.z, a1); a1 = fmaf(w1.w * m1.w, v1.w, a1);
        a2 = fmaf(w2.x * m2.x, v2.x, a2); a2 = fmaf(w2.y * m2.y, v2.y, a2);
        a2 = fmaf(w2.z * m2.z, v2.z, a2); a2 = fmaf(w2.w * m2.w, v2.w, a2);
        a3 = fmaf(w3.x * m3.x, v3.x, a3); a3 = fmaf(w3.y * m3.y, v3.y, a3);
        a3 = fmaf(w3.z * m3.z, v3.z, a3); a3 = fmaf(w3.w * m3.w, v3.w, a3);
    }

    float acc = (a0 + a1) + (a2 + a3);
#pragma unroll
    for (int o = 16; o; o >>= 1) acc += __shfl_xor_sync(0xffffffffu, acc, o);

    if (lane == 0) {
        const float spk = (acc > 1.0f) ? 1.0f : 0.0f;   // THRESH = 1.0
        if (OUT == 0)      g_s0[row] = spk;
        else if (OUT == 1) g_s1[row] = spk;
        else {
            const int T = Tp ? *Tp : 128;
            out[row] = spk / (float)T;                  // spikes only at t=0
        }
    }
}

extern "C" void kernel_launch(void* const* d_in, const int* in_sizes, int n_in,
                              void* d_out, int out_size) {
    const float* x  = (const float*)d_in[0];
    const float* u  = (const float*)d_in[1];
    const float* W0 = (const float*)d_in[2];
    const float* W1 = (const float*)d_in[3];
    const float* W2 = (const float*)d_in[4];
    const float* M0 = (const float*)d_in[5];
    const float* M1 = (const float*)d_in[6];
    const float* M2 = (const float*)d_in[7];
    const int*   T  = (n_in > 8) ? (const int*)d_in[8] : nullptr;
    float* out = (float*)d_out;

    const int grid = NDIM / WARPS_PER_BLOCK;   // 512 blocks, 1 warp per row
    enc_k<<<NDIM / 256, 256>>>(x, u);
    layer_k<0, 0><<<grid, WARPS_PER_BLOCK * 32>>>(W0, M0, nullptr, nullptr);
    layer_k<1, 1><<<grid, WARPS_PER_BLOCK * 32>>>(W1, M1, nullptr, nullptr);
    layer_k<2, 2><<<grid, WARPS_PER_BLOCK * 32>>>(W2, M2, T, out);
}

// round 5
// speedup vs baseline: 1.3480x; 1.1012x over previous
#include <cuda_runtime.h>

#define NDIM 4096

// Inter-layer spike vectors (scratch via __device__ globals — no allocation).
__device__ float g_enc[NDIM];
__device__ float g_s0[NDIM];
__device__ float g_s1[NDIM];

// Rate-coding encoder: enc_i = (u_i < x_i) ? 1 : 0.
__global__ void enc_k(const float* __restrict__ x, const float* __restrict__ u) {
    int i = blockIdx.x * blockDim.x + threadIdx.x;
    if (i < NDIM) g_enc[i] = (u[i] < x[i]) ? 1.0f : 0.0f;
}

// Masked matvec + threshold. One row per block (grid 4096), 256 threads.
// W/M streamed with __ldcs (read-once, evict-first) in two half-batches of
// 4 outstanding LDG.128 each; 2 independent FMA chains; single end reduce.
//  IN : 0 -> g_enc, 1 -> g_s0, 2 -> g_s1
//  OUT: 0 -> g_s0,  1 -> g_s1, 2 -> out[row] = spk / T
template<int IN, int OUT>
__global__ __launch_bounds__(256) void layer_k(const float* __restrict__ W,
                                               const float* __restrict__ M,
                                               const int* __restrict__ Tp,
                                               float* __restrict__ out) {
    const float* s = (IN == 0) ? g_enc : (IN == 1) ? g_s0 : g_s1;
    const int row = blockIdx.x;
    const float4* __restrict__ w4 =
        reinterpret_cast<const float4*>(W) + (size_t)row * (NDIM / 4);
    const float4* __restrict__ m4 =
        reinterpret_cast<const float4*>(M) + (size_t)row * (NDIM / 4);
    const float4* __restrict__ s4 = reinterpret_cast<const float4*>(s);

    float a0 = 0.0f, a1 = 0.0f;
#pragma unroll
    for (int k = 0; k < 4; k += 2) {
        const int i0 = threadIdx.x + (k + 0) * 256;
        const int i1 = threadIdx.x + (k + 1) * 256;
        // Front-batch 4 DRAM loads (2 rows of W, M interleaved).
        const float4 w0 = __ldcs(w4 + i0);
        const float4 m0 = __ldcs(m4 + i0);
        const float4 w1 = __ldcs(w4 + i1);
        const float4 m1 = __ldcs(m4 + i1);
        const float4 v0 = __ldg(s4 + i0);
        const float4 v1 = __ldg(s4 + i1);
        a0 = fmaf(w0.x * m0.x, v0.x, a0);
        a0 = fmaf(w0.y * m0.y, v0.y, a0);
        a0 = fmaf(w0.z * m0.z, v0.z, a0);
        a0 = fmaf(w0.w * m0.w, v0.w, a0);
        a1 = fmaf(w1.x * m1.x, v1.x, a1);
        a1 = fmaf(w1.y * m1.y, v1.y, a1);
        a1 = fmaf(w1.z * m1.z, v1.z, a1);
        a1 = fmaf(w1.w * m1.w, v1.w, a1);
    }

    float acc = a0 + a1;
#pragma unroll
    for (int o = 16; o; o >>= 1) acc += __shfl_xor_sync(0xffffffffu, acc, o);

    __shared__ float sm[8];
    if ((threadIdx.x & 31) == 0) sm[threadIdx.x >> 5] = acc;
    __syncthreads();

    if (threadIdx.x == 0) {
        float t = 0.0f;
#pragma unroll
        for (int i = 0; i < 8; i++) t += sm[i];
        const float spk = (t > 1.0f) ? 1.0f : 0.0f;   // THRESH = 1.0
        if (OUT == 0)      g_s0[row] = spk;
        else if (OUT == 1) g_s1[row] = spk;
        else {
            const int T = Tp ? *Tp : 128;
            out[row] = spk / (float)T;                // spikes only at t=0
        }
    }
}

extern "C" void kernel_launch(void* const* d_in, const int* in_sizes, int n_in,
                              void* d_out, int out_size) {
    const float* x  = (const float*)d_in[0];
    const float* u  = (const float*)d_in[1];
    const float* W0 = (const float*)d_in[2];
    const float* W1 = (const float*)d_in[3];
    const float* W2 = (const float*)d_in[4];
    const float* M0 = (const float*)d_in[5];
    const float* M1 = (const float*)d_in[6];
    const float* M2 = (const float*)d_in[7];
    const int*   T  = (n_in > 8) ? (const int*)d_in[8] : nullptr;
    float* out = (float*)d_out;

    enc_k<<<NDIM / 256, 256>>>(x, u);
    layer_k<0, 0><<<NDIM, 256>>>(W0, M0, nullptr, nullptr);
    layer_k<1, 1><<<NDIM, 256>>>(W1, M1, nullptr, nullptr);
    layer_k<2, 2><<<NDIM, 256>>>(W2, M2, T, out);
}